// round 1
// baseline (speedup 1.0000x reference)
#include <cuda_runtime.h>
#include <math.h>

#define NODES   100000
#define EDGES   400000
#define EMB     300
#define HID     600
#define NGRAPH  4096
#define NLAYERS 5
#define CH4     75          // EMB/4
#define HCH4    150         // HID/4
#define BN_EPS  1e-5f
#define INV_TEMP 25.0f      // 1/0.04

// ------------------------- scratch (device globals; no allocation) ----------
__device__ float g_h   [NODES * EMB];    // node features         (120 MB)
__device__ float g_agg [NODES * EMB];    // aggregation / proj out (120 MB)
__device__ float g_hid [NODES * HID];    // MLP hidden            (240 MB)
__device__ float g_f0  [NGRAPH * EMB];
__device__ float g_f1  [NGRAPH * EMB];
__device__ float g_pool[NGRAPH * EMB];
__device__ float g_cnt [NGRAPH];
__device__ float g_sum [EMB];
__device__ float g_sqs [EMB];

// ------------------------- h init: h = ae1[x0] + ae2[x1] --------------------
__global__ void k_init_h(const int* __restrict__ x,
                         const float* __restrict__ ae1,
                         const float* __restrict__ ae2) {
    int idx = blockIdx.x * blockDim.x + threadIdx.x;
    if (idx >= NODES * CH4) return;
    int node = idx / CH4, c = idx % CH4;
    int i0 = x[2 * node], i1 = x[2 * node + 1];
    float4 a = ((const float4*)ae1)[i0 * CH4 + c];
    float4 b = ((const float4*)ae2)[i1 * CH4 + c];
    ((float4*)g_h)[idx] = make_float4(a.x + b.x, a.y + b.y, a.z + b.z, a.w + b.w);
}

// ------------------------- agg = h + self_emb -------------------------------
__global__ void k_init_agg(const float* __restrict__ ee1,
                           const float* __restrict__ ee2, int layer) {
    int idx = blockIdx.x * blockDim.x + threadIdx.x;
    if (idx >= NODES * CH4) return;
    int c = idx % CH4;
    float4 s1 = ((const float4*)(ee1 + (layer * 6 + 4) * EMB))[c];
    float4 s2 = ((const float4*)(ee2 + (layer * 3 + 0) * EMB))[c];
    float4 h  = ((const float4*)g_h)[idx];
    ((float4*)g_agg)[idx] = make_float4(h.x + s1.x + s2.x, h.y + s1.y + s2.y,
                                        h.z + s1.z + s2.z, h.w + s1.w + s2.w);
}

// ------------------------- edge scatter: agg[dst] += h[src] + eemb ----------
__global__ void k_edge_scatter(const int* __restrict__ ei,
                               const int* __restrict__ ea,
                               const float* __restrict__ ee1,
                               const float* __restrict__ ee2, int layer) {
    __shared__ __align__(16) float se1[6 * EMB];
    __shared__ __align__(16) float se2[3 * EMB];
    const float* t1 = ee1 + layer * 6 * EMB;
    const float* t2 = ee2 + layer * 3 * EMB;
    for (int i = threadIdx.x; i < 6 * EMB; i += blockDim.x) se1[i] = t1[i];
    for (int i = threadIdx.x; i < 3 * EMB; i += blockDim.x) se2[i] = t2[i];
    __syncthreads();

    int lane  = threadIdx.x & 31;
    int warp  = (blockIdx.x * blockDim.x + threadIdx.x) >> 5;
    int nwarp = (gridDim.x * blockDim.x) >> 5;
    const float4* h4  = (const float4*)g_h;
    const float4* s14 = (const float4*)se1;
    const float4* s24 = (const float4*)se2;

    for (int e = warp; e < EDGES; e += nwarp) {
        int src = ei[e];
        int dst = ei[EDGES + e];
        int a0  = ea[2 * e];
        int a1  = ea[2 * e + 1];
        const float4* hs = h4 + (size_t)src * CH4;
        const float4* p1 = s14 + a0 * CH4;
        const float4* p2 = s24 + a1 * CH4;
        float* ad = g_agg + (size_t)dst * EMB;
        for (int c = lane; c < CH4; c += 32) {
            float4 hv = hs[c], v1 = p1[c], v2 = p2[c];
            atomicAdd(ad + 4 * c + 0, hv.x + v1.x + v2.x);
            atomicAdd(ad + 4 * c + 1, hv.y + v1.y + v2.y);
            atomicAdd(ad + 4 * c + 2, hv.z + v1.z + v2.z);
            atomicAdd(ad + 4 * c + 3, hv.w + v1.w + v2.w);
        }
    }
}

// ------------------------- generic guarded SGEMM + bias (+relu) -------------
// C[M,N] = A[M,K] @ B[K,N] + bias;  BM=BN=64, BK=16, 256 threads, 4x4/thread
__global__ void k_sgemm(const float* __restrict__ A, const float* __restrict__ B,
                        const float* __restrict__ bias, float* __restrict__ C,
                        int M, int N, int K, int doRelu) {
    __shared__ __align__(16) float As[16][64];
    __shared__ __align__(16) float Bs[16][64];
    int tx = threadIdx.x, ty = threadIdx.y;
    int tid = ty * 16 + tx;
    int rowBase = blockIdx.y * 64;
    int colBase = blockIdx.x * 64;
    float acc[4][4] = {};
    int nk = (K + 15) / 16;
    for (int kt = 0; kt < nk; kt++) {
        int k0 = kt * 16;
        {   // load A tile (transposed into As[k][m])
            int c = tid & 15, r0 = tid >> 4;
#pragma unroll
            for (int p = 0; p < 4; p++) {
                int r = r0 + p * 16;
                int gr = rowBase + r, gc = k0 + c;
                As[c][r] = (gr < M && gc < K) ? A[(size_t)gr * K + gc] : 0.f;
            }
        }
        {   // load B tile
            int n = tid & 63, kk0 = tid >> 6;
#pragma unroll
            for (int p = 0; p < 4; p++) {
                int kk = kk0 + p * 4;
                int gk = k0 + kk, gn = colBase + n;
                Bs[kk][n] = (gk < K && gn < N) ? B[(size_t)gk * N + gn] : 0.f;
            }
        }
        __syncthreads();
#pragma unroll
        for (int kk = 0; kk < 16; kk++) {
            float4 a = *(const float4*)&As[kk][ty * 4];
            float4 b = *(const float4*)&Bs[kk][tx * 4];
            float ar[4] = {a.x, a.y, a.z, a.w};
            float br[4] = {b.x, b.y, b.z, b.w};
#pragma unroll
            for (int i = 0; i < 4; i++)
#pragma unroll
                for (int j = 0; j < 4; j++) acc[i][j] += ar[i] * br[j];
        }
        __syncthreads();
    }
#pragma unroll
    for (int i = 0; i < 4; i++) {
        int gr = rowBase + ty * 4 + i;
        if (gr >= M) continue;
#pragma unroll
        for (int j = 0; j < 4; j++) {
            int gc = colBase + tx * 4 + j;
            if (gc >= N) continue;
            float v = acc[i][j] + bias[gc];
            if (doRelu) v = fmaxf(v, 0.f);
            C[(size_t)gr * N + gc] = v;
        }
    }
}

// ------------------------- batchnorm ---------------------------------------
__global__ void k_zero600() {
    int t = threadIdx.x;
    if (t < EMB) { g_sum[t] = 0.f; g_sqs[t] = 0.f; }
}

__global__ void k_bn_reduce() {
    int c = threadIdx.x;
    if (c >= EMB) return;
    int base = blockIdx.x * 256;
    float s = 0.f, q = 0.f;
    for (int r = 0; r < 256; r++) {
        int row = base + r;
        if (row < NODES) {
            float v = g_h[(size_t)row * EMB + c];
            s += v; q += v * v;
        }
    }
    atomicAdd(&g_sum[c], s);
    atomicAdd(&g_sqs[c], q);
}

__global__ void k_bn_norm(const float* __restrict__ gamma,
                          const float* __restrict__ beta, int doRelu) {
    int idx = blockIdx.x * blockDim.x + threadIdx.x;
    if (idx >= NODES * CH4) return;
    int c = idx % CH4;
    const float invN = 1.f / (float)NODES;
    float4 v  = ((const float4*)g_h)[idx];
    float4 s  = ((const float4*)g_sum)[c];
    float4 q  = ((const float4*)g_sqs)[c];
    float4 gm = ((const float4*)gamma)[c];
    float4 bt = ((const float4*)beta)[c];
    float m, var, is;
    m = s.x * invN; var = q.x * invN - m * m; is = rsqrtf(var + BN_EPS);
    v.x = (v.x - m) * is * gm.x + bt.x;
    m = s.y * invN; var = q.y * invN - m * m; is = rsqrtf(var + BN_EPS);
    v.y = (v.y - m) * is * gm.y + bt.y;
    m = s.z * invN; var = q.z * invN - m * m; is = rsqrtf(var + BN_EPS);
    v.z = (v.z - m) * is * gm.z + bt.z;
    m = s.w * invN; var = q.w * invN - m * m; is = rsqrtf(var + BN_EPS);
    v.w = (v.w - m) * is * gm.w + bt.w;
    if (doRelu) {
        v.x = fmaxf(v.x, 0.f); v.y = fmaxf(v.y, 0.f);
        v.z = fmaxf(v.z, 0.f); v.w = fmaxf(v.w, 0.f);
    }
    ((float4*)g_h)[idx] = v;
}

// ------------------------- pooling + normalize ------------------------------
__global__ void k_zero_pool() {
    int idx = blockIdx.x * blockDim.x + threadIdx.x;
    if (idx < NGRAPH * EMB) g_pool[idx] = 0.f;
    if (idx < NGRAPH) g_cnt[idx] = 0.f;
}

__global__ void k_pool_scatter(const int* __restrict__ batch) {
    int idx = blockIdx.x * blockDim.x + threadIdx.x;
    if (idx >= NODES * CH4) return;
    int node = idx / CH4, c = idx % CH4;
    int b = batch[node];
    float4 v = ((const float4*)g_agg)[idx];   // projector output lives in g_agg
    float* d = g_pool + (size_t)b * EMB + 4 * c;
    atomicAdd(d + 0, v.x); atomicAdd(d + 1, v.y);
    atomicAdd(d + 2, v.z); atomicAdd(d + 3, v.w);
}

__global__ void k_count(const int* __restrict__ batch) {
    int i = blockIdx.x * blockDim.x + threadIdx.x;
    if (i < NODES) atomicAdd(&g_cnt[batch[i]], 1.f);
}

__global__ void k_finalize(int br) {
    int warp = (blockIdx.x * blockDim.x + threadIdx.x) >> 5;
    int lane = threadIdx.x & 31;
    if (warp >= NGRAPH) return;
    float* fout = br ? g_f1 : g_f0;
    float ic = 1.f / fmaxf(g_cnt[warp], 1.f);
    float sq = 0.f;
    for (int c = lane; c < EMB; c += 32) {
        float v = g_pool[(size_t)warp * EMB + c] * ic;
        sq += v * v;
    }
#pragma unroll
    for (int o = 16; o > 0; o >>= 1) sq += __shfl_xor_sync(0xffffffffu, sq, o);
    float rn = 1.f / fmaxf(sqrtf(sq), 1e-12f);
    for (int c = lane; c < EMB; c += 32)
        fout[(size_t)warp * EMB + c] = g_pool[(size_t)warp * EMB + c] * ic * rn;
}

// ------------------------- logits: out = (f0 @ f1^T) * 25 -------------------
__global__ void k_logits(float* __restrict__ out) {
    __shared__ __align__(16) float As[16][64];
    __shared__ __align__(16) float Bs[16][64];
    int tx = threadIdx.x, ty = threadIdx.y;
    int tid = ty * 16 + tx;
    int rowBase = blockIdx.y * 64;
    int colBase = blockIdx.x * 64;
    float acc[4][4] = {};
    for (int kt = 0; kt < (EMB + 15) / 16; kt++) {
        int k0 = kt * 16;
        int c = tid & 15, r0 = tid >> 4;
#pragma unroll
        for (int p = 0; p < 4; p++) {
            int r = r0 + p * 16;
            int gc = k0 + c;
            As[c][r] = (gc < EMB) ? g_f0[(size_t)(rowBase + r) * EMB + gc] : 0.f;
            Bs[c][r] = (gc < EMB) ? g_f1[(size_t)(colBase + r) * EMB + gc] : 0.f;
        }
        __syncthreads();
#pragma unroll
        for (int kk = 0; kk < 16; kk++) {
            float4 a = *(const float4*)&As[kk][ty * 4];
            float4 b = *(const float4*)&Bs[kk][tx * 4];
            float ar[4] = {a.x, a.y, a.z, a.w};
            float br[4] = {b.x, b.y, b.z, b.w};
#pragma unroll
            for (int i = 0; i < 4; i++)
#pragma unroll
                for (int j = 0; j < 4; j++) acc[i][j] += ar[i] * br[j];
        }
        __syncthreads();
    }
#pragma unroll
    for (int i = 0; i < 4; i++)
#pragma unroll
        for (int j = 0; j < 4; j++)
            out[(size_t)(rowBase + ty * 4 + i) * NGRAPH + colBase + tx * 4 + j] =
                acc[i][j] * INV_TEMP;
}

// ------------------------- driver -------------------------------------------
extern "C" void kernel_launch(void* const* d_in, const int* in_sizes, int n_in,
                              void* d_out, int out_size) {
    (void)in_sizes; (void)n_in; (void)out_size;
    const int*   x[2]  = {(const int*)d_in[0], (const int*)d_in[4]};
    const int*   ei[2] = {(const int*)d_in[1], (const int*)d_in[5]};
    const int*   ea[2] = {(const int*)d_in[2], (const int*)d_in[6]};
    const int*   bt[2] = {(const int*)d_in[3], (const int*)d_in[7]};
    const float* ae1   = (const float*)d_in[8];
    const float* ae2   = (const float*)d_in[9];
    const float* ee1   = (const float*)d_in[10];
    const float* ee2   = (const float*)d_in[11];
    const float* w1    = (const float*)d_in[12];
    const float* b1    = (const float*)d_in[13];
    const float* w2    = (const float*)d_in[14];
    const float* b2    = (const float*)d_in[15];
    const float* gamma = (const float*)d_in[16];
    const float* beta  = (const float*)d_in[17];
    const float* pw    = (const float*)d_in[18];
    const float* pb    = (const float*)d_in[19];
    float* out = (float*)d_out;

    float *d_h, *d_agg, *d_hid;
    cudaGetSymbolAddress((void**)&d_h,   g_h);
    cudaGetSymbolAddress((void**)&d_agg, g_agg);
    cudaGetSymbolAddress((void**)&d_hid, g_hid);

    const int NCH = NODES * CH4;
    dim3 gblk(16, 16);
    dim3 grid1((HID + 63) / 64, (NODES + 63) / 64);   // GEMM1
    dim3 grid2((EMB + 63) / 64, (NODES + 63) / 64);   // GEMM2 / projector

    for (int br = 0; br < 2; br++) {
        k_init_h<<<(NCH + 255) / 256, 256>>>(x[br], ae1, ae2);
        for (int l = 0; l < NLAYERS; l++) {
            k_init_agg<<<(NCH + 255) / 256, 256>>>(ee1, ee2, l);
            k_edge_scatter<<<2048, 256>>>(ei[br], ea[br], ee1, ee2, l);
            k_sgemm<<<grid1, gblk>>>(d_agg, w1 + (size_t)l * EMB * HID,
                                     b1 + (size_t)l * HID, d_hid,
                                     NODES, HID, EMB, 1);
            k_sgemm<<<grid2, gblk>>>(d_hid, w2 + (size_t)l * HID * EMB,
                                     b2 + (size_t)l * EMB, d_h,
                                     NODES, EMB, HID, 0);
            k_zero600<<<1, 640>>>();
            k_bn_reduce<<<(NODES + 255) / 256, 320>>>();
            k_bn_norm<<<(NCH + 255) / 256, 256>>>(gamma + (size_t)l * EMB,
                                                  beta + (size_t)l * EMB,
                                                  l != NLAYERS - 1);
        }
        // projector: p = h @ pw + pb  (into g_agg)
        k_sgemm<<<grid2, gblk>>>(d_h, pw, pb, d_agg, NODES, EMB, EMB, 0);
        k_zero_pool<<<(NGRAPH * EMB + 255) / 256, 256>>>();
        k_pool_scatter<<<(NCH + 255) / 256, 256>>>(bt[br]);
        k_count<<<(NODES + 255) / 256, 256>>>(bt[br]);
        k_finalize<<<(NGRAPH * 32 + 255) / 256, 256>>>(br);
    }
    k_logits<<<dim3(NGRAPH / 64, NGRAPH / 64), gblk>>>(out);
}

// round 2
// speedup vs baseline: 1.0409x; 1.0409x over previous
#include <cuda_runtime.h>
#include <math.h>

#define NODES   100000
#define EDGES   400000
#define EMB     300
#define HID     600
#define NGRAPH  4096
#define NLAYERS 5
#define CH4     75          // EMB/4
#define BN_EPS  1e-5f
#define INV_TEMP 25.0f      // 1/0.04

// ------------------------- scratch (device globals; no allocation) ----------
__device__ float g_h   [NODES * EMB];
__device__ float g_agg [NODES * EMB];
__device__ float g_hid [NODES * HID];
__device__ float g_f0  [NGRAPH * EMB];
__device__ float g_f1  [NGRAPH * EMB];
__device__ float g_pool[NGRAPH * EMB];
__device__ float g_cnt [NGRAPH];
__device__ float g_sum [EMB];
__device__ float g_sqs [EMB];

// ------------------------- vector reduction helper --------------------------
__device__ __forceinline__ void red4(float* p, float x, float y, float z, float w) {
    unsigned long long gp = __cvta_generic_to_global(p);
    asm volatile("red.global.add.v4.f32 [%0], {%1,%2,%3,%4};"
                 :: "l"(gp), "f"(x), "f"(y), "f"(z), "f"(w) : "memory");
}

// ------------------------- h init: h = ae1[x0]+ae2[x1]; agg = h + self0 -----
__global__ void k_init_h(const int* __restrict__ x,
                         const float* __restrict__ ae1,
                         const float* __restrict__ ae2,
                         const float* __restrict__ s1,
                         const float* __restrict__ s2) {
    int idx = blockIdx.x * blockDim.x + threadIdx.x;
    if (idx >= NODES * CH4) return;
    int node = idx / CH4, c = idx % CH4;
    int i0 = x[2 * node], i1 = x[2 * node + 1];
    float4 a = ((const float4*)ae1)[i0 * CH4 + c];
    float4 b = ((const float4*)ae2)[i1 * CH4 + c];
    float4 h = make_float4(a.x + b.x, a.y + b.y, a.z + b.z, a.w + b.w);
    ((float4*)g_h)[idx] = h;
    float4 v1 = ((const float4*)s1)[c];
    float4 v2 = ((const float4*)s2)[c];
    ((float4*)g_agg)[idx] = make_float4(h.x + v1.x + v2.x, h.y + v1.y + v2.y,
                                        h.z + v1.z + v2.z, h.w + v1.w + v2.w);
}

// ------------------------- edge scatter: agg[dst] += h[src] + eemb ----------
__global__ void k_edge_scatter(const int* __restrict__ ei,
                               const int* __restrict__ ea,
                               const float* __restrict__ ee1,
                               const float* __restrict__ ee2, int layer) {
    __shared__ __align__(16) float se1[6 * EMB];
    __shared__ __align__(16) float se2[3 * EMB];
    const float* t1 = ee1 + layer * 6 * EMB;
    const float* t2 = ee2 + layer * 3 * EMB;
    for (int i = threadIdx.x; i < 6 * EMB; i += blockDim.x) se1[i] = t1[i];
    for (int i = threadIdx.x; i < 3 * EMB; i += blockDim.x) se2[i] = t2[i];
    __syncthreads();

    int lane  = threadIdx.x & 31;
    int warp  = (blockIdx.x * blockDim.x + threadIdx.x) >> 5;
    int nwarp = (gridDim.x * blockDim.x) >> 5;
    const float4* h4  = (const float4*)g_h;
    const float4* s14 = (const float4*)se1;
    const float4* s24 = (const float4*)se2;

    for (int e = warp; e < EDGES; e += nwarp) {
        int src = ei[e];
        int dst = ei[EDGES + e];
        int a0  = ea[2 * e];
        int a1  = ea[2 * e + 1];
        const float4* hs = h4 + (size_t)src * CH4;
        const float4* p1 = s14 + a0 * CH4;
        const float4* p2 = s24 + a1 * CH4;
        float* ad = g_agg + (size_t)dst * EMB;
        for (int c = lane; c < CH4; c += 32) {
            float4 hv = hs[c], v1 = p1[c], v2 = p2[c];
            red4(ad + 4 * c, hv.x + v1.x + v2.x, hv.y + v1.y + v2.y,
                             hv.z + v1.z + v2.z, hv.w + v1.w + v2.w);
        }
    }
}

// ------------------------- SGEMM 128x64x16, 8x4/thread, double-buffered -----
// C[M,N] = A[M,K] @ B[K,N] + bias (+relu).  Requires K%4==0, N%4==0.
#define BM 128
#define BN 64
#define BK 16

__global__ __launch_bounds__(256, 3)
void k_sgemm(const float* __restrict__ A, const float* __restrict__ B,
             const float* __restrict__ bias, float* __restrict__ C,
             int M, int N, int K, int doRelu) {
    __shared__ __align__(16) float As[2][BK][BM + 4];
    __shared__ __align__(16) float Bs[2][BK][BN];
    int tid = threadIdx.x;
    int tx = tid & 15;          // 0..15 : col group (4 cols)
    int ty = tid >> 4;          // 0..15 : row group (8 rows)
    int rowBase = blockIdx.y * BM;
    int colBase = blockIdx.x * BN;

    int af = tid & 3;           // which k-float4 in A tile
    int ar = tid >> 2;          // A row 0..63 (and +64)
    int bk = tid >> 4;          // B tile k-row
    int bc = (tid & 15) * 4;    // B tile col

    const int nk = (K + BK - 1) / BK;
    float acc[8][4] = {};
    float4 pa0, pa1, pb;

    // ---- tile-0 load ----
    {
        int gk = 4 * af;
        bool kok = gk < K;
        int gr0 = rowBase + ar, gr1 = gr0 + 64;
        pa0 = make_float4(0, 0, 0, 0);
        pa1 = make_float4(0, 0, 0, 0);
        if (kok && gr0 < M) pa0 = *(const float4*)(A + (size_t)gr0 * K + gk);
        if (kok && gr1 < M) pa1 = *(const float4*)(A + (size_t)gr1 * K + gk);
        pb = make_float4(0, 0, 0, 0);
        int gc = colBase + bc;
        if (bk < K && gc < N) pb = *(const float4*)(B + (size_t)bk * N + gc);
    }
    int buf = 0;
#pragma unroll
    for (int i = 0; i < 4; i++) {
        As[0][af * 4 + i][ar]      = ((float*)&pa0)[i];
        As[0][af * 4 + i][ar + 64] = ((float*)&pa1)[i];
    }
    *(float4*)&Bs[0][bk][bc] = pb;
    __syncthreads();

    for (int kt = 0; kt < nk; kt++) {
        if (kt + 1 < nk) {
            int k0 = (kt + 1) * BK;
            int gk = k0 + 4 * af;
            bool kok = gk < K;
            int gr0 = rowBase + ar, gr1 = gr0 + 64;
            pa0 = make_float4(0, 0, 0, 0);
            pa1 = make_float4(0, 0, 0, 0);
            if (kok && gr0 < M) pa0 = *(const float4*)(A + (size_t)gr0 * K + gk);
            if (kok && gr1 < M) pa1 = *(const float4*)(A + (size_t)gr1 * K + gk);
            pb = make_float4(0, 0, 0, 0);
            int gkb = k0 + bk, gc = colBase + bc;
            if (gkb < K && gc < N) pb = *(const float4*)(B + (size_t)gkb * N + gc);
        }
#pragma unroll
        for (int kk = 0; kk < BK; kk++) {
            float4 a0 = *(const float4*)&As[buf][kk][ty * 8];
            float4 a1 = *(const float4*)&As[buf][kk][ty * 8 + 4];
            float4 b  = *(const float4*)&Bs[buf][kk][tx * 4];
            float ar8[8] = {a0.x, a0.y, a0.z, a0.w, a1.x, a1.y, a1.z, a1.w};
            float br4[4] = {b.x, b.y, b.z, b.w};
#pragma unroll
            for (int i = 0; i < 8; i++)
#pragma unroll
                for (int j = 0; j < 4; j++) acc[i][j] += ar8[i] * br4[j];
        }
        if (kt + 1 < nk) {
            buf ^= 1;
#pragma unroll
            for (int i = 0; i < 4; i++) {
                As[buf][af * 4 + i][ar]      = ((float*)&pa0)[i];
                As[buf][af * 4 + i][ar + 64] = ((float*)&pa1)[i];
            }
            *(float4*)&Bs[buf][bk][bc] = pb;
            __syncthreads();
        }
    }

    int gc = colBase + tx * 4;
    if (gc < N) {
        float4 bv = *(const float4*)(bias + gc);
#pragma unroll
        for (int i = 0; i < 8; i++) {
            int gr = rowBase + ty * 8 + i;
            if (gr >= M) continue;
            float4 o = make_float4(acc[i][0] + bv.x, acc[i][1] + bv.y,
                                   acc[i][2] + bv.z, acc[i][3] + bv.w);
            if (doRelu) {
                o.x = fmaxf(o.x, 0.f); o.y = fmaxf(o.y, 0.f);
                o.z = fmaxf(o.z, 0.f); o.w = fmaxf(o.w, 0.f);
            }
            *(float4*)(C + (size_t)gr * N + gc) = o;
        }
    }
}

// ------------------------- batchnorm ---------------------------------------
__global__ void k_zero600() {
    int t = threadIdx.x;
    if (t < EMB) { g_sum[t] = 0.f; g_sqs[t] = 0.f; }
}

__global__ void k_bn_reduce() {
    int c = threadIdx.x;
    if (c >= EMB) return;
    int base = blockIdx.x * 256;
    float s = 0.f, q = 0.f;
    for (int r = 0; r < 256; r++) {
        int row = base + r;
        if (row < NODES) {
            float v = g_h[(size_t)row * EMB + c];
            s += v; q += v * v;
        }
    }
    atomicAdd(&g_sum[c], s);
    atomicAdd(&g_sqs[c], q);
}

// normalize h; if s1!=null also write g_agg = out + self_emb(next layer)
__global__ void k_bn_norm(const float* __restrict__ gamma,
                          const float* __restrict__ beta,
                          const float* __restrict__ s1,
                          const float* __restrict__ s2, int doRelu) {
    int idx = blockIdx.x * blockDim.x + threadIdx.x;
    if (idx >= NODES * CH4) return;
    int c = idx % CH4;
    const float invN = 1.f / (float)NODES;
    float4 v  = ((const float4*)g_h)[idx];
    float4 s  = ((const float4*)g_sum)[c];
    float4 q  = ((const float4*)g_sqs)[c];
    float4 gm = ((const float4*)gamma)[c];
    float4 bt = ((const float4*)beta)[c];
    float m, var, is;
    m = s.x * invN; var = q.x * invN - m * m; is = rsqrtf(var + BN_EPS);
    v.x = (v.x - m) * is * gm.x + bt.x;
    m = s.y * invN; var = q.y * invN - m * m; is = rsqrtf(var + BN_EPS);
    v.y = (v.y - m) * is * gm.y + bt.y;
    m = s.z * invN; var = q.z * invN - m * m; is = rsqrtf(var + BN_EPS);
    v.z = (v.z - m) * is * gm.z + bt.z;
    m = s.w * invN; var = q.w * invN - m * m; is = rsqrtf(var + BN_EPS);
    v.w = (v.w - m) * is * gm.w + bt.w;
    if (doRelu) {
        v.x = fmaxf(v.x, 0.f); v.y = fmaxf(v.y, 0.f);
        v.z = fmaxf(v.z, 0.f); v.w = fmaxf(v.w, 0.f);
    }
    ((float4*)g_h)[idx] = v;
    if (s1) {
        float4 v1 = ((const float4*)s1)[c];
        float4 v2 = ((const float4*)s2)[c];
        ((float4*)g_agg)[idx] = make_float4(v.x + v1.x + v2.x, v.y + v1.y + v2.y,
                                            v.z + v1.z + v2.z, v.w + v1.w + v2.w);
    }
}

// ------------------------- pooling + normalize ------------------------------
__global__ void k_zero_pool() {
    int idx = blockIdx.x * blockDim.x + threadIdx.x;
    if (idx < NGRAPH * EMB) g_pool[idx] = 0.f;
    if (idx < NGRAPH) g_cnt[idx] = 0.f;
}

__global__ void k_pool_scatter(const int* __restrict__ batch) {
    int idx = blockIdx.x * blockDim.x + threadIdx.x;
    if (idx >= NODES * CH4) return;
    int node = idx / CH4, c = idx % CH4;
    int b = batch[node];
    float4 v = ((const float4*)g_agg)[idx];   // projector output lives in g_agg
    red4(g_pool + (size_t)b * EMB + 4 * c, v.x, v.y, v.z, v.w);
}

__global__ void k_count(const int* __restrict__ batch) {
    int i = blockIdx.x * blockDim.x + threadIdx.x;
    if (i < NODES) atomicAdd(&g_cnt[batch[i]], 1.f);
}

__global__ void k_finalize(int br) {
    int warp = (blockIdx.x * blockDim.x + threadIdx.x) >> 5;
    int lane = threadIdx.x & 31;
    if (warp >= NGRAPH) return;
    float* fout = br ? g_f1 : g_f0;
    float ic = 1.f / fmaxf(g_cnt[warp], 1.f);
    float sq = 0.f;
    for (int c = lane; c < EMB; c += 32) {
        float v = g_pool[(size_t)warp * EMB + c] * ic;
        sq += v * v;
    }
#pragma unroll
    for (int o = 16; o > 0; o >>= 1) sq += __shfl_xor_sync(0xffffffffu, sq, o);
    float rn = 1.f / fmaxf(sqrtf(sq), 1e-12f);
    for (int c = lane; c < EMB; c += 32)
        fout[(size_t)warp * EMB + c] = g_pool[(size_t)warp * EMB + c] * ic * rn;
}

// ------------------------- logits: out = (f0 @ f1^T) * 25 -------------------
__global__ void k_logits(float* __restrict__ out) {
    __shared__ __align__(16) float As[16][64];
    __shared__ __align__(16) float Bs[16][64];
    int tx = threadIdx.x, ty = threadIdx.y;
    int tid = ty * 16 + tx;
    int rowBase = blockIdx.y * 64;
    int colBase = blockIdx.x * 64;
    float acc[4][4] = {};
    for (int kt = 0; kt < (EMB + 15) / 16; kt++) {
        int k0 = kt * 16;
        int c = tid & 15, r0 = tid >> 4;
#pragma unroll
        for (int p = 0; p < 4; p++) {
            int r = r0 + p * 16;
            int gc = k0 + c;
            As[c][r] = (gc < EMB) ? g_f0[(size_t)(rowBase + r) * EMB + gc] : 0.f;
            Bs[c][r] = (gc < EMB) ? g_f1[(size_t)(colBase + r) * EMB + gc] : 0.f;
        }
        __syncthreads();
#pragma unroll
        for (int kk = 0; kk < 16; kk++) {
            float4 a = *(const float4*)&As[kk][ty * 4];
            float4 b = *(const float4*)&Bs[kk][tx * 4];
            float ar[4] = {a.x, a.y, a.z, a.w};
            float br[4] = {b.x, b.y, b.z, b.w};
#pragma unroll
            for (int i = 0; i < 4; i++)
#pragma unroll
                for (int j = 0; j < 4; j++) acc[i][j] += ar[i] * br[j];
        }
        __syncthreads();
    }
#pragma unroll
    for (int i = 0; i < 4; i++)
#pragma unroll
        for (int j = 0; j < 4; j++)
            out[(size_t)(rowBase + ty * 4 + i) * NGRAPH + colBase + tx * 4 + j] =
                acc[i][j] * INV_TEMP;
}

// ------------------------- driver -------------------------------------------
extern "C" void kernel_launch(void* const* d_in, const int* in_sizes, int n_in,
                              void* d_out, int out_size) {
    (void)in_sizes; (void)n_in; (void)out_size;
    const int*   x[2]  = {(const int*)d_in[0], (const int*)d_in[4]};
    const int*   ei[2] = {(const int*)d_in[1], (const int*)d_in[5]};
    const int*   ea[2] = {(const int*)d_in[2], (const int*)d_in[6]};
    const int*   bt[2] = {(const int*)d_in[3], (const int*)d_in[7]};
    const float* ae1   = (const float*)d_in[8];
    const float* ae2   = (const float*)d_in[9];
    const float* ee1   = (const float*)d_in[10];
    const float* ee2   = (const float*)d_in[11];
    const float* w1    = (const float*)d_in[12];
    const float* b1    = (const float*)d_in[13];
    const float* w2    = (const float*)d_in[14];
    const float* b2    = (const float*)d_in[15];
    const float* gamma = (const float*)d_in[16];
    const float* beta  = (const float*)d_in[17];
    const float* pw    = (const float*)d_in[18];
    const float* pb    = (const float*)d_in[19];
    float* out = (float*)d_out;

    float *d_h, *d_agg, *d_hid;
    cudaGetSymbolAddress((void**)&d_h,   g_h);
    cudaGetSymbolAddress((void**)&d_agg, g_agg);
    cudaGetSymbolAddress((void**)&d_hid, g_hid);

    const int NCH = NODES * CH4;
    dim3 grid1((HID + BN - 1) / BN, (NODES + BM - 1) / BM);   // GEMM1
    dim3 grid2((EMB + BN - 1) / BN, (NODES + BM - 1) / BM);   // GEMM2 / proj

    // self-loop embedding pointers per layer: ee1[l][4], ee2[l][0]
    const float* selfs1[NLAYERS];
    const float* selfs2[NLAYERS];
    for (int l = 0; l < NLAYERS; l++) {
        selfs1[l] = ee1 + (size_t)(l * 6 + 4) * EMB;
        selfs2[l] = ee2 + (size_t)(l * 3 + 0) * EMB;
    }

    for (int br = 0; br < 2; br++) {
        k_init_h<<<(NCH + 255) / 256, 256>>>(x[br], ae1, ae2, selfs1[0], selfs2[0]);
        for (int l = 0; l < NLAYERS; l++) {
            k_edge_scatter<<<2048, 256>>>(ei[br], ea[br], ee1, ee2, l);
            k_sgemm<<<grid1, 256>>>(d_agg, w1 + (size_t)l * EMB * HID,
                                    b1 + (size_t)l * HID, d_hid,
                                    NODES, HID, EMB, 1);
            k_sgemm<<<grid2, 256>>>(d_hid, w2 + (size_t)l * HID * EMB,
                                    b2 + (size_t)l * EMB, d_h,
                                    NODES, EMB, HID, 0);
            k_zero600<<<1, 640>>>();
            k_bn_reduce<<<(NODES + 255) / 256, 320>>>();
            int last = (l == NLAYERS - 1);
            k_bn_norm<<<(NCH + 255) / 256, 256>>>(
                gamma + (size_t)l * EMB, beta + (size_t)l * EMB,
                last ? nullptr : selfs1[l + 1], last ? nullptr : selfs2[l + 1],
                !last);
        }
        // projector: p = h @ pw + pb  (into g_agg)
        k_sgemm<<<grid2, 256>>>(d_h, pw, pb, d_agg, NODES, EMB, EMB, 0);
        k_zero_pool<<<(NGRAPH * EMB + 255) / 256, 256>>>();
        k_pool_scatter<<<(NCH + 255) / 256, 256>>>(bt[br]);
        k_count<<<(NODES + 255) / 256, 256>>>(bt[br]);
        k_finalize<<<(NGRAPH * 32 + 255) / 256, 256>>>(br);
    }
    k_logits<<<dim3(NGRAPH / 64, NGRAPH / 64), dim3(16, 16)>>>(out);
}

// round 3
// speedup vs baseline: 1.6776x; 1.6116x over previous
#include <cuda_runtime.h>
#include <math.h>

#define NODES   100000
#define EDGES   400000
#define EMB     300
#define HID     600
#define NGRAPH  4096
#define NLAYERS 5
#define CH4     75          // EMB/4
#define BN_EPS  1e-5f
#define INV_TEMP 25.0f      // 1/0.04

// ------------------------- scratch (device globals; no allocation) ----------
__device__ float g_h   [NODES * EMB];
__device__ float g_agg [NODES * EMB];
__device__ float g_hid [NODES * HID];
__device__ float g_f0  [NGRAPH * EMB];
__device__ float g_f1  [NGRAPH * EMB];
__device__ float g_pool[NGRAPH * EMB];
__device__ float g_cnt [NGRAPH];
__device__ float g_sum [EMB];
__device__ float g_sqs [EMB];

// ------------------------- helpers ------------------------------------------
__device__ __forceinline__ void red4(float* p, float x, float y, float z, float w) {
    unsigned long long gp = __cvta_generic_to_global(p);
    asm volatile("red.global.add.v4.f32 [%0], {%1,%2,%3,%4};"
                 :: "l"(gp), "f"(x), "f"(y), "f"(z), "f"(w) : "memory");
}

__device__ __forceinline__ float to_tf32(float x) {
    float r;
    asm("cvt.rna.tf32.f32 %0, %1;" : "=f"(r) : "f"(x));
    return r;
}

__device__ __forceinline__ void mma_tf32(float* c, const unsigned* a, const unsigned* b) {
    asm volatile(
        "mma.sync.aligned.m16n8k8.row.col.f32.tf32.tf32.f32 "
        "{%0,%1,%2,%3},{%4,%5,%6,%7},{%8,%9},{%0,%1,%2,%3};"
        : "+f"(c[0]), "+f"(c[1]), "+f"(c[2]), "+f"(c[3])
        : "r"(a[0]), "r"(a[1]), "r"(a[2]), "r"(a[3]), "r"(b[0]), "r"(b[1]));
}

// ------------------------- h init: h = ae1[x0]+ae2[x1]; agg = h + self0 -----
__global__ void k_init_h(const int* __restrict__ x,
                         const float* __restrict__ ae1,
                         const float* __restrict__ ae2,
                         const float* __restrict__ s1,
                         const float* __restrict__ s2) {
    int idx = blockIdx.x * blockDim.x + threadIdx.x;
    if (idx >= NODES * CH4) return;
    int node = idx / CH4, c = idx % CH4;
    int i0 = x[2 * node], i1 = x[2 * node + 1];
    float4 a = ((const float4*)ae1)[i0 * CH4 + c];
    float4 b = ((const float4*)ae2)[i1 * CH4 + c];
    float4 h = make_float4(a.x + b.x, a.y + b.y, a.z + b.z, a.w + b.w);
    ((float4*)g_h)[idx] = h;
    float4 v1 = ((const float4*)s1)[c];
    float4 v2 = ((const float4*)s2)[c];
    ((float4*)g_agg)[idx] = make_float4(h.x + v1.x + v2.x, h.y + v1.y + v2.y,
                                        h.z + v1.z + v2.z, h.w + v1.w + v2.w);
}

// ------------------------- edge scatter: agg[dst] += h[src] + eemb ----------
__global__ void k_edge_scatter(const int* __restrict__ ei,
                               const int* __restrict__ ea,
                               const float* __restrict__ ee1,
                               const float* __restrict__ ee2, int layer) {
    __shared__ __align__(16) float se1[6 * EMB];
    __shared__ __align__(16) float se2[3 * EMB];
    const float* t1 = ee1 + layer * 6 * EMB;
    const float* t2 = ee2 + layer * 3 * EMB;
    for (int i = threadIdx.x; i < 6 * EMB; i += blockDim.x) se1[i] = t1[i];
    for (int i = threadIdx.x; i < 3 * EMB; i += blockDim.x) se2[i] = t2[i];
    __syncthreads();

    int lane  = threadIdx.x & 31;
    int warp  = (blockIdx.x * blockDim.x + threadIdx.x) >> 5;
    int nwarp = (gridDim.x * blockDim.x) >> 5;
    const float4* h4  = (const float4*)g_h;
    const float4* s14 = (const float4*)se1;
    const float4* s24 = (const float4*)se2;

    for (int e = warp; e < EDGES; e += nwarp) {
        int src = ei[e];
        int dst = ei[EDGES + e];
        int a0  = ea[2 * e];
        int a1  = ea[2 * e + 1];
        const float4* hs = h4 + (size_t)src * CH4;
        const float4* p1 = s14 + a0 * CH4;
        const float4* p2 = s24 + a1 * CH4;
        float* ad = g_agg + (size_t)dst * EMB;
        for (int c = lane; c < CH4; c += 32) {
            float4 hv = hs[c], v1 = p1[c], v2 = p2[c];
            red4(ad + 4 * c, hv.x + v1.x + v2.x, hv.y + v1.y + v2.y,
                             hv.z + v1.z + v2.z, hv.w + v1.w + v2.w);
        }
    }
}

// ------------------------- tensor-core GEMM (3xTF32) -------------------------
// C[M,N] = A[M,K] @ B[K,N] + bias (+relu).  Requires K%4==0, N%4==0.
#define BM 128
#define BN 64
#define BK 16
#define ASTR 136            // 136 % 32 == 8 -> conflict-free frag loads
#define BSTR 72             //  72 % 32 == 8
#define ABUF (BK * ASTR)    // floats per A buffer
#define BBUF (BK * BSTR)
// smem: Ah[2] Al[2] Bh[2] Bl[2]
#define SMEM_TC ((4 * ABUF + 4 * BBUF) * 4)

__global__ __launch_bounds__(256)
void k_gemm_tc(const float* __restrict__ A, const float* __restrict__ B,
               const float* __restrict__ bias, float* __restrict__ C,
               int M, int N, int K, int doRelu) {
    extern __shared__ float sm[];
    float* Ah = sm;
    float* Al = sm + 2 * ABUF;
    float* Bh = sm + 4 * ABUF;
    float* Bl = sm + 4 * ABUF + 2 * BBUF;

    int tid  = threadIdx.x;
    int lane = tid & 31;
    int warp = tid >> 5;
    int wm = warp >> 1;           // 0..3 -> m offset wm*32
    int wn = warp & 1;            // 0..1 -> n offset wn*32
    int g  = lane >> 2;           // 0..7
    int t  = lane & 3;            // 0..3
    int rowBase = blockIdx.y * BM;
    int colBase = blockIdx.x * BN;

    // global->smem mapping
    int af = tid & 3;             // k-group in A tile
    int ar = tid >> 2;            // A row 0..63 (and +64)
    int bk = tid >> 4;            // B tile k-row 0..15
    int bc = (tid & 15) * 4;      // B tile col

    const int nk = (K + BK - 1) / BK;
    float acc[2][4][4] = {};
    float4 pa0, pa1, pb;

    // ---- prefetch tile 0 ----
    {
        int gk = 4 * af;
        bool kok = gk < K;
        int gr0 = rowBase + ar, gr1 = gr0 + 64;
        pa0 = make_float4(0, 0, 0, 0);
        pa1 = make_float4(0, 0, 0, 0);
        if (kok && gr0 < M) pa0 = *(const float4*)(A + (size_t)gr0 * K + gk);
        if (kok && gr1 < M) pa1 = *(const float4*)(A + (size_t)gr1 * K + gk);
        pb = make_float4(0, 0, 0, 0);
        int gc = colBase + bc;
        if (bk < K && gc < N) pb = *(const float4*)(B + (size_t)bk * N + gc);
    }
    int buf = 0;
    {
        float* ah = Ah; float* al = Al;
#pragma unroll
        for (int i = 0; i < 4; i++) {
            float v0 = ((float*)&pa0)[i], v1 = ((float*)&pa1)[i];
            float h0 = to_tf32(v0), h1 = to_tf32(v1);
            int k = af * 4 + i;
            ah[k * ASTR + ar]      = h0;  al[k * ASTR + ar]      = to_tf32(v0 - h0);
            ah[k * ASTR + ar + 64] = h1;  al[k * ASTR + ar + 64] = to_tf32(v1 - h1);
        }
#pragma unroll
        for (int i = 0; i < 4; i++) {
            float v = ((float*)&pb)[i];
            float h = to_tf32(v);
            Bh[bk * BSTR + bc + i] = h;
            Bl[bk * BSTR + bc + i] = to_tf32(v - h);
        }
    }
    __syncthreads();

    for (int kt = 0; kt < nk; kt++) {
        if (kt + 1 < nk) {
            int k0 = (kt + 1) * BK;
            int gk = k0 + 4 * af;
            bool kok = gk < K;
            int gr0 = rowBase + ar, gr1 = gr0 + 64;
            pa0 = make_float4(0, 0, 0, 0);
            pa1 = make_float4(0, 0, 0, 0);
            if (kok && gr0 < M) pa0 = *(const float4*)(A + (size_t)gr0 * K + gk);
            if (kok && gr1 < M) pa1 = *(const float4*)(A + (size_t)gr1 * K + gk);
            pb = make_float4(0, 0, 0, 0);
            int gkb = k0 + bk, gc = colBase + bc;
            if (gkb < K && gc < N) pb = *(const float4*)(B + (size_t)gkb * N + gc);
        }
        // ---- compute on buf ----
        const float* ah = Ah + buf * ABUF;
        const float* al = Al + buf * ABUF;
        const float* bh = Bh + buf * BBUF;
        const float* bl = Bl + buf * BBUF;
#pragma unroll
        for (int kk = 0; kk < 2; kk++) {
            const float* ah0 = ah + (kk * 8 + t) * ASTR;
            const float* ah1 = ah + (kk * 8 + t + 4) * ASTR;
            const float* al0 = al + (kk * 8 + t) * ASTR;
            const float* al1 = al + (kk * 8 + t + 4) * ASTR;
            unsigned fah[2][4], fal[2][4];
#pragma unroll
            for (int i = 0; i < 2; i++) {
                int r = wm * 32 + i * 16 + g;
                fah[i][0] = __float_as_uint(ah0[r]);
                fah[i][1] = __float_as_uint(ah0[r + 8]);
                fah[i][2] = __float_as_uint(ah1[r]);
                fah[i][3] = __float_as_uint(ah1[r + 8]);
                fal[i][0] = __float_as_uint(al0[r]);
                fal[i][1] = __float_as_uint(al0[r + 8]);
                fal[i][2] = __float_as_uint(al1[r]);
                fal[i][3] = __float_as_uint(al1[r + 8]);
            }
            const float* bh0 = bh + (kk * 8 + t) * BSTR;
            const float* bh1 = bh + (kk * 8 + t + 4) * BSTR;
            const float* bl0 = bl + (kk * 8 + t) * BSTR;
            const float* bl1 = bl + (kk * 8 + t + 4) * BSTR;
            unsigned fbh[4][2], fbl[4][2];
#pragma unroll
            for (int j = 0; j < 4; j++) {
                int c = wn * 32 + j * 8 + g;
                fbh[j][0] = __float_as_uint(bh0[c]);
                fbh[j][1] = __float_as_uint(bh1[c]);
                fbl[j][0] = __float_as_uint(bl0[c]);
                fbl[j][1] = __float_as_uint(bl1[c]);
            }
#pragma unroll
            for (int i = 0; i < 2; i++)
#pragma unroll
                for (int j = 0; j < 4; j++) {
                    mma_tf32(acc[i][j], fal[i], fbh[j]);   // lo*hi
                    mma_tf32(acc[i][j], fah[i], fbl[j]);   // hi*lo
                    mma_tf32(acc[i][j], fah[i], fbh[j]);   // hi*hi
                }
        }
        if (kt + 1 < nk) {
            buf ^= 1;
            float* ahw = Ah + buf * ABUF;
            float* alw = Al + buf * ABUF;
            float* bhw = Bh + buf * BBUF;
            float* blw = Bl + buf * BBUF;
            __syncthreads();
#pragma unroll
            for (int i = 0; i < 4; i++) {
                float v0 = ((float*)&pa0)[i], v1 = ((float*)&pa1)[i];
                float h0 = to_tf32(v0), h1 = to_tf32(v1);
                int k = af * 4 + i;
                ahw[k * ASTR + ar]      = h0;  alw[k * ASTR + ar]      = to_tf32(v0 - h0);
                ahw[k * ASTR + ar + 64] = h1;  alw[k * ASTR + ar + 64] = to_tf32(v1 - h1);
            }
#pragma unroll
            for (int i = 0; i < 4; i++) {
                float v = ((float*)&pb)[i];
                float h = to_tf32(v);
                bhw[bk * BSTR + bc + i] = h;
                blw[bk * BSTR + bc + i] = to_tf32(v - h);
            }
            __syncthreads();
        }
    }

    // ---- epilogue ----
#pragma unroll
    for (int i = 0; i < 2; i++) {
#pragma unroll
        for (int j = 0; j < 4; j++) {
            int gc = colBase + wn * 32 + j * 8 + t * 2;
            if (gc >= N) continue;
            float b0 = bias[gc], b1 = bias[gc + 1];
            int gr0 = rowBase + wm * 32 + i * 16 + g;
            int gr1 = gr0 + 8;
            float o0 = acc[i][j][0] + b0, o1 = acc[i][j][1] + b1;
            float o2 = acc[i][j][2] + b0, o3 = acc[i][j][3] + b1;
            if (doRelu) {
                o0 = fmaxf(o0, 0.f); o1 = fmaxf(o1, 0.f);
                o2 = fmaxf(o2, 0.f); o3 = fmaxf(o3, 0.f);
            }
            if (gr0 < M) *(float2*)(C + (size_t)gr0 * N + gc) = make_float2(o0, o1);
            if (gr1 < M) *(float2*)(C + (size_t)gr1 * N + gc) = make_float2(o2, o3);
        }
    }
}

// ------------------------- batchnorm ---------------------------------------
__global__ void k_zero600() {
    int t = threadIdx.x;
    if (t < EMB) { g_sum[t] = 0.f; g_sqs[t] = 0.f; }
}

__global__ void k_bn_reduce() {
    int c = threadIdx.x;
    if (c >= EMB) return;
    int base = blockIdx.x * 256;
    float s = 0.f, q = 0.f;
    for (int r = 0; r < 256; r++) {
        int row = base + r;
        if (row < NODES) {
            float v = g_h[(size_t)row * EMB + c];
            s += v; q += v * v;
        }
    }
    atomicAdd(&g_sum[c], s);
    atomicAdd(&g_sqs[c], q);
}

__global__ void k_bn_norm(const float* __restrict__ gamma,
                          const float* __restrict__ beta,
                          const float* __restrict__ s1,
                          const float* __restrict__ s2, int doRelu) {
    int idx = blockIdx.x * blockDim.x + threadIdx.x;
    if (idx >= NODES * CH4) return;
    int c = idx % CH4;
    const float invN = 1.f / (float)NODES;
    float4 v  = ((const float4*)g_h)[idx];
    float4 s  = ((const float4*)g_sum)[c];
    float4 q  = ((const float4*)g_sqs)[c];
    float4 gm = ((const float4*)gamma)[c];
    float4 bt = ((const float4*)beta)[c];
    float m, var, is;
    m = s.x * invN; var = q.x * invN - m * m; is = rsqrtf(var + BN_EPS);
    v.x = (v.x - m) * is * gm.x + bt.x;
    m = s.y * invN; var = q.y * invN - m * m; is = rsqrtf(var + BN_EPS);
    v.y = (v.y - m) * is * gm.y + bt.y;
    m = s.z * invN; var = q.z * invN - m * m; is = rsqrtf(var + BN_EPS);
    v.z = (v.z - m) * is * gm.z + bt.z;
    m = s.w * invN; var = q.w * invN - m * m; is = rsqrtf(var + BN_EPS);
    v.w = (v.w - m) * is * gm.w + bt.w;
    if (doRelu) {
        v.x = fmaxf(v.x, 0.f); v.y = fmaxf(v.y, 0.f);
        v.z = fmaxf(v.z, 0.f); v.w = fmaxf(v.w, 0.f);
    }
    ((float4*)g_h)[idx] = v;
    if (s1) {
        float4 v1 = ((const float4*)s1)[c];
        float4 v2 = ((const float4*)s2)[c];
        ((float4*)g_agg)[idx] = make_float4(v.x + v1.x + v2.x, v.y + v1.y + v2.y,
                                            v.z + v1.z + v2.z, v.w + v1.w + v2.w);
    }
}

// ------------------------- pooling + normalize ------------------------------
__global__ void k_zero_pool() {
    int idx = blockIdx.x * blockDim.x + threadIdx.x;
    if (idx < NGRAPH * EMB) g_pool[idx] = 0.f;
    if (idx < NGRAPH) g_cnt[idx] = 0.f;
}

__global__ void k_pool_scatter(const int* __restrict__ batch) {
    int idx = blockIdx.x * blockDim.x + threadIdx.x;
    if (idx >= NODES * CH4) return;
    int node = idx / CH4, c = idx % CH4;
    int b = batch[node];
    float4 v = ((const float4*)g_agg)[idx];
    red4(g_pool + (size_t)b * EMB + 4 * c, v.x, v.y, v.z, v.w);
}

__global__ void k_count(const int* __restrict__ batch) {
    int i = blockIdx.x * blockDim.x + threadIdx.x;
    if (i < NODES) atomicAdd(&g_cnt[batch[i]], 1.f);
}

__global__ void k_finalize(int br) {
    int warp = (blockIdx.x * blockDim.x + threadIdx.x) >> 5;
    int lane = threadIdx.x & 31;
    if (warp >= NGRAPH) return;
    float* fout = br ? g_f1 : g_f0;
    float ic = 1.f / fmaxf(g_cnt[warp], 1.f);
    float sq = 0.f;
    for (int c = lane; c < EMB; c += 32) {
        float v = g_pool[(size_t)warp * EMB + c] * ic;
        sq += v * v;
    }
#pragma unroll
    for (int o = 16; o > 0; o >>= 1) sq += __shfl_xor_sync(0xffffffffu, sq, o);
    float rn = 1.f / fmaxf(sqrtf(sq), 1e-12f);
    for (int c = lane; c < EMB; c += 32)
        fout[(size_t)warp * EMB + c] = g_pool[(size_t)warp * EMB + c] * ic * rn;
}

// ------------------------- logits: out = (f0 @ f1^T) * 25 (exact fp32) ------
__global__ void k_logits(float* __restrict__ out) {
    __shared__ __align__(16) float As[16][64];
    __shared__ __align__(16) float Bs[16][64];
    int tx = threadIdx.x, ty = threadIdx.y;
    int tid = ty * 16 + tx;
    int rowBase = blockIdx.y * 64;
    int colBase = blockIdx.x * 64;
    float acc[4][4] = {};
    for (int kt = 0; kt < (EMB + 15) / 16; kt++) {
        int k0 = kt * 16;
        int c = tid & 15, r0 = tid >> 4;
#pragma unroll
        for (int p = 0; p < 4; p++) {
            int r = r0 + p * 16;
            int gc = k0 + c;
            As[c][r] = (gc < EMB) ? g_f0[(size_t)(rowBase + r) * EMB + gc] : 0.f;
            Bs[c][r] = (gc < EMB) ? g_f1[(size_t)(colBase + r) * EMB + gc] : 0.f;
        }
        __syncthreads();
#pragma unroll
        for (int kk = 0; kk < 16; kk++) {
            float4 a = *(const float4*)&As[kk][ty * 4];
            float4 b = *(const float4*)&Bs[kk][tx * 4];
            float ar[4] = {a.x, a.y, a.z, a.w};
            float br[4] = {b.x, b.y, b.z, b.w};
#pragma unroll
            for (int i = 0; i < 4; i++)
#pragma unroll
                for (int j = 0; j < 4; j++) acc[i][j] += ar[i] * br[j];
        }
        __syncthreads();
    }
#pragma unroll
    for (int i = 0; i < 4; i++)
#pragma unroll
        for (int j = 0; j < 4; j++)
            out[(size_t)(rowBase + ty * 4 + i) * NGRAPH + colBase + tx * 4 + j] =
                acc[i][j] * INV_TEMP;
}

// ------------------------- driver -------------------------------------------
extern "C" void kernel_launch(void* const* d_in, const int* in_sizes, int n_in,
                              void* d_out, int out_size) {
    (void)in_sizes; (void)n_in; (void)out_size;
    const int*   x[2]  = {(const int*)d_in[0], (const int*)d_in[4]};
    const int*   ei[2] = {(const int*)d_in[1], (const int*)d_in[5]};
    const int*   ea[2] = {(const int*)d_in[2], (const int*)d_in[6]};
    const int*   bt[2] = {(const int*)d_in[3], (const int*)d_in[7]};
    const float* ae1   = (const float*)d_in[8];
    const float* ae2   = (const float*)d_in[9];
    const float* ee1   = (const float*)d_in[10];
    const float* ee2   = (const float*)d_in[11];
    const float* w1    = (const float*)d_in[12];
    const float* b1    = (const float*)d_in[13];
    const float* w2    = (const float*)d_in[14];
    const float* b2    = (const float*)d_in[15];
    const float* gamma = (const float*)d_in[16];
    const float* beta  = (const float*)d_in[17];
    const float* pw    = (const float*)d_in[18];
    const float* pb    = (const float*)d_in[19];
    float* out = (float*)d_out;

    float *d_h, *d_agg, *d_hid;
    cudaGetSymbolAddress((void**)&d_h,   g_h);
    cudaGetSymbolAddress((void**)&d_agg, g_agg);
    cudaGetSymbolAddress((void**)&d_hid, g_hid);

    cudaFuncSetAttribute(k_gemm_tc, cudaFuncAttributeMaxDynamicSharedMemorySize,
                         SMEM_TC);

    const int NCH = NODES * CH4;
    dim3 grid1((HID + BN - 1) / BN, (NODES + BM - 1) / BM);
    dim3 grid2((EMB + BN - 1) / BN, (NODES + BM - 1) / BM);

    const float* selfs1[NLAYERS];
    const float* selfs2[NLAYERS];
    for (int l = 0; l < NLAYERS; l++) {
        selfs1[l] = ee1 + (size_t)(l * 6 + 4) * EMB;
        selfs2[l] = ee2 + (size_t)(l * 3 + 0) * EMB;
    }

    for (int br = 0; br < 2; br++) {
        k_init_h<<<(NCH + 255) / 256, 256>>>(x[br], ae1, ae2, selfs1[0], selfs2[0]);
        for (int l = 0; l < NLAYERS; l++) {
            k_edge_scatter<<<2048, 256>>>(ei[br], ea[br], ee1, ee2, l);
            k_gemm_tc<<<grid1, 256, SMEM_TC>>>(d_agg, w1 + (size_t)l * EMB * HID,
                                               b1 + (size_t)l * HID, d_hid,
                                               NODES, HID, EMB, 1);
            k_gemm_tc<<<grid2, 256, SMEM_TC>>>(d_hid, w2 + (size_t)l * HID * EMB,
                                               b2 + (size_t)l * EMB, d_h,
                                               NODES, EMB, HID, 0);
            k_zero600<<<1, 640>>>();
            k_bn_reduce<<<(NODES + 255) / 256, 320>>>();
            int last = (l == NLAYERS - 1);
            k_bn_norm<<<(NCH + 255) / 256, 256>>>(
                gamma + (size_t)l * EMB, beta + (size_t)l * EMB,
                last ? nullptr : selfs1[l + 1], last ? nullptr : selfs2[l + 1],
                !last);
        }
        k_gemm_tc<<<grid2, 256, SMEM_TC>>>(d_h, pw, pb, d_agg, NODES, EMB, EMB, 0);
        k_zero_pool<<<(NGRAPH * EMB + 255) / 256, 256>>>();
        k_pool_scatter<<<(NCH + 255) / 256, 256>>>(bt[br]);
        k_count<<<(NODES + 255) / 256, 256>>>(bt[br]);
        k_finalize<<<(NGRAPH * 32 + 255) / 256, 256>>>(br);
    }
    k_logits<<<dim3(NGRAPH / 64, NGRAPH / 64), dim3(16, 16)>>>(out);
}

// round 6
// speedup vs baseline: 2.7736x; 1.6534x over previous
#include <cuda_runtime.h>
#include <cuda_bf16.h>
#include <math.h>

#define NODES   100000
#define EDGES   400000
#define EMB     300
#define HID     600
#define NGRAPH  4096
#define NLAYERS 5
#define CH4     75          // EMB/4
#define BN_EPS  1e-5f
#define INV_TEMP 25.0f      // 1/0.04

// ------------------------- scratch (device globals; no allocation) ----------
__device__ float g_h   [NODES * EMB];
__device__ float g_agg [NODES * EMB];
__device__ float g_hid [NODES * HID];
__device__ float g_f0  [NGRAPH * EMB];
__device__ float g_f1  [NGRAPH * EMB];
__device__ float g_pool[NGRAPH * EMB];
__device__ float g_cnt [NGRAPH];
__device__ float g_sum [EMB];
__device__ float g_sqs [EMB];

// ------------------------- helpers ------------------------------------------
__device__ __forceinline__ void red4(float* p, float x, float y, float z, float w) {
    unsigned long long gp = __cvta_generic_to_global(p);
    asm volatile("red.global.add.v4.f32 [%0], {%1,%2,%3,%4};"
                 :: "l"(gp), "f"(x), "f"(y), "f"(z), "f"(w) : "memory");
}

// pack two floats into bf16x2: element0 (low 16) = lo, element1 (high) = hi
__device__ __forceinline__ unsigned pack_bf16(float lo, float hi) {
    unsigned r;
    asm("cvt.rn.bf16x2.f32 %0, %1, %2;" : "=r"(r) : "f"(hi), "f"(lo));
    return r;
}
__device__ __forceinline__ float bf_lo(unsigned w) { return __uint_as_float(w << 16); }
__device__ __forceinline__ float bf_hi(unsigned w) { return __uint_as_float(w & 0xffff0000u); }

__device__ __forceinline__ void mma_bf16(float* c, const unsigned* a, const unsigned* b) {
    asm volatile(
        "mma.sync.aligned.m16n8k16.row.col.f32.bf16.bf16.f32 "
        "{%0,%1,%2,%3},{%4,%5,%6,%7},{%8,%9},{%0,%1,%2,%3};"
        : "+f"(c[0]), "+f"(c[1]), "+f"(c[2]), "+f"(c[3])
        : "r"(a[0]), "r"(a[1]), "r"(a[2]), "r"(a[3]), "r"(b[0]), "r"(b[1]));
}

// ------------------------- h init: h = ae1[x0]+ae2[x1]; agg = h + self0 -----
__global__ void k_init_h(const int* __restrict__ x,
                         const float* __restrict__ ae1,
                         const float* __restrict__ ae2,
                         const float* __restrict__ s1,
                         const float* __restrict__ s2) {
    int idx = blockIdx.x * blockDim.x + threadIdx.x;
    if (idx >= NODES * CH4) return;
    int node = idx / CH4, c = idx % CH4;
    int i0 = x[2 * node], i1 = x[2 * node + 1];
    float4 a = ((const float4*)ae1)[i0 * CH4 + c];
    float4 b = ((const float4*)ae2)[i1 * CH4 + c];
    float4 h = make_float4(a.x + b.x, a.y + b.y, a.z + b.z, a.w + b.w);
    ((float4*)g_h)[idx] = h;
    float4 v1 = ((const float4*)s1)[c];
    float4 v2 = ((const float4*)s2)[c];
    ((float4*)g_agg)[idx] = make_float4(h.x + v1.x + v2.x, h.y + v1.y + v2.y,
                                        h.z + v1.z + v2.z, h.w + v1.w + v2.w);
}

// ------------------------- edge scatter: agg[dst] += h[src] + eemb ----------
__global__ void k_edge_scatter(const int* __restrict__ ei,
                               const int* __restrict__ ea,
                               const float* __restrict__ ee1,
                               const float* __restrict__ ee2, int layer) {
    __shared__ __align__(16) float se1[6 * EMB];
    __shared__ __align__(16) float se2[3 * EMB];
    const float* t1 = ee1 + layer * 6 * EMB;
    const float* t2 = ee2 + layer * 3 * EMB;
    for (int i = threadIdx.x; i < 6 * EMB; i += blockDim.x) se1[i] = t1[i];
    for (int i = threadIdx.x; i < 3 * EMB; i += blockDim.x) se2[i] = t2[i];
    __syncthreads();

    int lane  = threadIdx.x & 31;
    int warp  = (blockIdx.x * blockDim.x + threadIdx.x) >> 5;
    int nwarp = (gridDim.x * blockDim.x) >> 5;
    const float4* h4  = (const float4*)g_h;
    const float4* s14 = (const float4*)se1;
    const float4* s24 = (const float4*)se2;

    for (int e = warp; e < EDGES; e += nwarp) {
        int src = ei[e];
        int dst = ei[EDGES + e];
        int a0  = ea[2 * e];
        int a1  = ea[2 * e + 1];
        const float4* hs = h4 + (size_t)src * CH4;
        const float4* p1 = s14 + a0 * CH4;
        const float4* p2 = s24 + a1 * CH4;
        float* ad = g_agg + (size_t)dst * EMB;
        for (int c = lane; c < CH4; c += 32) {
            float4 hv = hs[c], v1 = p1[c], v2 = p2[c];
            red4(ad + 4 * c, hv.x + v1.x + v2.x, hv.y + v1.y + v2.y,
                             hv.z + v1.z + v2.z, hv.w + v1.w + v2.w);
        }
    }
}

// ------------------------- tensor-core GEMM (3x BF16 split) ------------------
// C[M,N] = A[M,K] @ B[K,N] + bias (+relu).  Requires N%4==0, K%2==0.
// smem stores bf16x2 words packed along k (element0 = even k).
#define BM 128
#define BN 64
#define BK 16
#define ASTR 136            // uint32 stride; 136%32==8 -> conflict-free frags
#define BSTR 72
#define ABUF (8 * ASTR)     // 8 k-pairs per tile
#define BBUF (8 * BSTR)
#define SMEM_TC ((4 * ABUF + 4 * BBUF) * 4)

__global__ __launch_bounds__(256)
void k_gemm_tc(const float* __restrict__ A, const float* __restrict__ B,
               const float* __restrict__ bias, float* __restrict__ C,
               int M, int N, int K, int doRelu) {
    extern __shared__ unsigned smu[];
    unsigned* Ah = smu;                    // [2][8][ASTR]
    unsigned* Al = smu + 2 * ABUF;
    unsigned* Bh = smu + 4 * ABUF;         // [2][8][BSTR]
    unsigned* Bl = smu + 4 * ABUF + 2 * BBUF;

    int tid  = threadIdx.x;
    int lane = tid & 31;
    int warp = tid >> 5;
    int wm = warp >> 1;            // m offset wm*32
    int wn = warp & 1;             // n offset wn*32
    int g  = lane >> 2;            // 0..7
    int t  = lane & 3;             // 0..3
    int rowBase = blockIdx.y * BM;
    int colBase = blockIdx.x * BN;

    // global->smem mapping
    int af = tid & 3;              // k-group of 4 in A tile
    int ar = tid >> 2;             // A row 0..63 (and +64)
    int bk2 = (tid & 127) >> 4;    // B k-pair 0..7   (threads 0..127 only)
    int bc  = (tid & 15) * 4;      // B col group

    const int nk = (K + BK - 1) / BK;
    float acc[2][4][4] = {};
    float4 pa0, pa1, pb0, pb1;

    // ---- prefetch tile 0 ----
    {
        int gk = 4 * af;
        bool kok = gk < K;
        int gr0 = rowBase + ar, gr1 = gr0 + 64;
        pa0 = make_float4(0, 0, 0, 0);
        pa1 = make_float4(0, 0, 0, 0);
        if (kok && gr0 < M) pa0 = *(const float4*)(A + (size_t)gr0 * K + gk);
        if (kok && gr1 < M) pa1 = *(const float4*)(A + (size_t)gr1 * K + gk);
        pb0 = make_float4(0, 0, 0, 0);
        pb1 = make_float4(0, 0, 0, 0);
        if (tid < 128) {
            int k0 = 2 * bk2, gc = colBase + bc;
            if (gc < N) {
                if (k0 < K)     pb0 = *(const float4*)(B + (size_t)k0 * N + gc);
                if (k0 + 1 < K) pb1 = *(const float4*)(B + (size_t)(k0 + 1) * N + gc);
            }
        }
    }
    int buf = 0;
    {
        // A: pack (k,k+1) pairs along k
        const float* v0 = (const float*)&pa0;
        const float* v1 = (const float*)&pa1;
#pragma unroll
        for (int p = 0; p < 2; p++) {
            int kp = af * 2 + p;
            unsigned h0 = pack_bf16(v0[2 * p], v0[2 * p + 1]);
            unsigned h1 = pack_bf16(v1[2 * p], v1[2 * p + 1]);
            Ah[kp * ASTR + ar]      = h0;
            Ah[kp * ASTR + ar + 64] = h1;
            Al[kp * ASTR + ar]      = pack_bf16(v0[2*p] - bf_lo(h0), v0[2*p+1] - bf_hi(h0));
            Al[kp * ASTR + ar + 64] = pack_bf16(v1[2*p] - bf_lo(h1), v1[2*p+1] - bf_hi(h1));
        }
        if (tid < 128) {
            const float* b0 = (const float*)&pb0;
            const float* b1 = (const float*)&pb1;
#pragma unroll
            for (int i = 0; i < 4; i++) {
                unsigned h = pack_bf16(b0[i], b1[i]);
                Bh[bk2 * BSTR + bc + i] = h;
                Bl[bk2 * BSTR + bc + i] = pack_bf16(b0[i] - bf_lo(h), b1[i] - bf_hi(h));
            }
        }
    }
    __syncthreads();

    for (int kt = 0; kt < nk; kt++) {
        if (kt + 1 < nk) {
            int k0t = (kt + 1) * BK;
            int gk = k0t + 4 * af;
            bool kok = gk < K;
            int gr0 = rowBase + ar, gr1 = gr0 + 64;
            pa0 = make_float4(0, 0, 0, 0);
            pa1 = make_float4(0, 0, 0, 0);
            if (kok && gr0 < M) pa0 = *(const float4*)(A + (size_t)gr0 * K + gk);
            if (kok && gr1 < M) pa1 = *(const float4*)(A + (size_t)gr1 * K + gk);
            pb0 = make_float4(0, 0, 0, 0);
            pb1 = make_float4(0, 0, 0, 0);
            if (tid < 128) {
                int k0 = k0t + 2 * bk2, gc = colBase + bc;
                if (gc < N) {
                    if (k0 < K)     pb0 = *(const float4*)(B + (size_t)k0 * N + gc);
                    if (k0 + 1 < K) pb1 = *(const float4*)(B + (size_t)(k0 + 1) * N + gc);
                }
            }
        }
        // ---- compute on buf (one k16 chunk) ----
        {
            const unsigned* ah = Ah + buf * ABUF;
            const unsigned* al = Al + buf * ABUF;
            const unsigned* bh = Bh + buf * BBUF;
            const unsigned* bl = Bl + buf * BBUF;
            unsigned Afh[2][4], Afl[2][4];
#pragma unroll
            for (int i = 0; i < 2; i++) {
                int m = wm * 32 + i * 16 + g;
                Afh[i][0] = ah[t * ASTR + m];
                Afh[i][1] = ah[t * ASTR + m + 8];
                Afh[i][2] = ah[(t + 4) * ASTR + m];
                Afh[i][3] = ah[(t + 4) * ASTR + m + 8];
                Afl[i][0] = al[t * ASTR + m];
                Afl[i][1] = al[t * ASTR + m + 8];
                Afl[i][2] = al[(t + 4) * ASTR + m];
                Afl[i][3] = al[(t + 4) * ASTR + m + 8];
            }
            unsigned Bfh[4][2], Bfl[4][2];
#pragma unroll
            for (int j = 0; j < 4; j++) {
                int n = wn * 32 + j * 8 + g;
                Bfh[j][0] = bh[t * BSTR + n];
                Bfh[j][1] = bh[(t + 4) * BSTR + n];
                Bfl[j][0] = bl[t * BSTR + n];
                Bfl[j][1] = bl[(t + 4) * BSTR + n];
            }
#pragma unroll
            for (int i = 0; i < 2; i++)
#pragma unroll
                for (int j = 0; j < 4; j++) {
                    mma_bf16(acc[i][j], Afl[i], Bfh[j]);   // lo*hi
                    mma_bf16(acc[i][j], Afh[i], Bfl[j]);   // hi*lo
                    mma_bf16(acc[i][j], Afh[i], Bfh[j]);   // hi*hi
                }
        }
        if (kt + 1 < nk) {
            buf ^= 1;
            unsigned* ahw = Ah + buf * ABUF;
            unsigned* alw = Al + buf * ABUF;
            unsigned* bhw = Bh + buf * BBUF;
            unsigned* blw = Bl + buf * BBUF;
            __syncthreads();
            const float* v0 = (const float*)&pa0;
            const float* v1 = (const float*)&pa1;
#pragma unroll
            for (int p = 0; p < 2; p++) {
                int kp = af * 2 + p;
                unsigned h0 = pack_bf16(v0[2 * p], v0[2 * p + 1]);
                unsigned h1 = pack_bf16(v1[2 * p], v1[2 * p + 1]);
                ahw[kp * ASTR + ar]      = h0;
                ahw[kp * ASTR + ar + 64] = h1;
                alw[kp * ASTR + ar]      = pack_bf16(v0[2*p] - bf_lo(h0), v0[2*p+1] - bf_hi(h0));
                alw[kp * ASTR + ar + 64] = pack_bf16(v1[2*p] - bf_lo(h1), v1[2*p+1] - bf_hi(h1));
            }
            if (tid < 128) {
                const float* b0 = (const float*)&pb0;
                const float* b1 = (const float*)&pb1;
#pragma unroll
                for (int i = 0; i < 4; i++) {
                    unsigned h = pack_bf16(b0[i], b1[i]);
                    bhw[bk2 * BSTR + bc + i] = h;
                    blw[bk2 * BSTR + bc + i] = pack_bf16(b0[i] - bf_lo(h), b1[i] - bf_hi(h));
                }
            }
            __syncthreads();
        }
    }

    // ---- epilogue ----
#pragma unroll
    for (int i = 0; i < 2; i++) {
#pragma unroll
        for (int j = 0; j < 4; j++) {
            int gc = colBase + wn * 32 + j * 8 + t * 2;
            if (gc >= N) continue;
            float b0 = bias[gc], b1 = bias[gc + 1];
            int gr0 = rowBase + wm * 32 + i * 16 + g;
            int gr1 = gr0 + 8;
            float o0 = acc[i][j][0] + b0, o1 = acc[i][j][1] + b1;
            float o2 = acc[i][j][2] + b0, o3 = acc[i][j][3] + b1;
            if (doRelu) {
                o0 = fmaxf(o0, 0.f); o1 = fmaxf(o1, 0.f);
                o2 = fmaxf(o2, 0.f); o3 = fmaxf(o3, 0.f);
            }
            if (gr0 < M) *(float2*)(C + (size_t)gr0 * N + gc) = make_float2(o0, o1);
            if (gr1 < M) *(float2*)(C + (size_t)gr1 * N + gc) = make_float2(o2, o3);
        }
    }
}

// ------------------------- batchnorm ---------------------------------------
__global__ void k_zero600() {
    int t = threadIdx.x;
    if (t < EMB) { g_sum[t] = 0.f; g_sqs[t] = 0.f; }
}

__global__ void k_bn_reduce() {
    int c = threadIdx.x;
    if (c >= EMB) return;
    int base = blockIdx.x * 256;
    float s = 0.f, q = 0.f;
    for (int r = 0; r < 256; r++) {
        int row = base + r;
        if (row < NODES) {
            float v = g_h[(size_t)row * EMB + c];
            s += v; q += v * v;
        }
    }
    atomicAdd(&g_sum[c], s);
    atomicAdd(&g_sqs[c], q);
}

__global__ void k_bn_norm(const float* __restrict__ gamma,
                          const float* __restrict__ beta,
                          const float* __restrict__ s1,
                          const float* __restrict__ s2, int doRelu) {
    int idx = blockIdx.x * blockDim.x + threadIdx.x;
    if (idx >= NODES * CH4) return;
    int c = idx % CH4;
    const float invN = 1.f / (float)NODES;
    float4 v  = ((const float4*)g_h)[idx];
    float4 s  = ((const float4*)g_sum)[c];
    float4 q  = ((const float4*)g_sqs)[c];
    float4 gm = ((const float4*)gamma)[c];
    float4 bt = ((const float4*)beta)[c];
    float m, var, is;
    m = s.x * invN; var = q.x * invN - m * m; is = rsqrtf(var + BN_EPS);
    v.x = (v.x - m) * is * gm.x + bt.x;
    m = s.y * invN; var = q.y * invN - m * m; is = rsqrtf(var + BN_EPS);
    v.y = (v.y - m) * is * gm.y + bt.y;
    m = s.z * invN; var = q.z * invN - m * m; is = rsqrtf(var + BN_EPS);
    v.z = (v.z - m) * is * gm.z + bt.z;
    m = s.w * invN; var = q.w * invN - m * m; is = rsqrtf(var + BN_EPS);
    v.w = (v.w - m) * is * gm.w + bt.w;
    if (doRelu) {
        v.x = fmaxf(v.x, 0.f); v.y = fmaxf(v.y, 0.f);
        v.z = fmaxf(v.z, 0.f); v.w = fmaxf(v.w, 0.f);
    }
    ((float4*)g_h)[idx] = v;
    if (s1) {
        float4 v1 = ((const float4*)s1)[c];
        float4 v2 = ((const float4*)s2)[c];
        ((float4*)g_agg)[idx] = make_float4(v.x + v1.x + v2.x, v.y + v1.y + v2.y,
                                            v.z + v1.z + v2.z, v.w + v1.w + v2.w);
    }
}

// ------------------------- pooling + normalize ------------------------------
__global__ void k_zero_pool() {
    int idx = blockIdx.x * blockDim.x + threadIdx.x;
    if (idx < NGRAPH * EMB) g_pool[idx] = 0.f;
    if (idx < NGRAPH) g_cnt[idx] = 0.f;
}

__global__ void k_pool_scatter(const int* __restrict__ batch) {
    int idx = blockIdx.x * blockDim.x + threadIdx.x;
    if (idx >= NODES * CH4) return;
    int node = idx / CH4, c = idx % CH4;
    int b = batch[node];
    float4 v = ((const float4*)g_agg)[idx];
    red4(g_pool + (size_t)b * EMB + 4 * c, v.x, v.y, v.z, v.w);
}

__global__ void k_count(const int* __restrict__ batch) {
    int i = blockIdx.x * blockDim.x + threadIdx.x;
    if (i < NODES) atomicAdd(&g_cnt[batch[i]], 1.f);
}

__global__ void k_finalize(int br) {
    int warp = (blockIdx.x * blockDim.x + threadIdx.x) >> 5;
    int lane = threadIdx.x & 31;
    if (warp >= NGRAPH) return;
    float* fout = br ? g_f1 : g_f0;
    float ic = 1.f / fmaxf(g_cnt[warp], 1.f);
    float sq = 0.f;
    for (int c = lane; c < EMB; c += 32) {
        float v = g_pool[(size_t)warp * EMB + c] * ic;
        sq += v * v;
    }
#pragma unroll
    for (int o = 16; o > 0; o >>= 1) sq += __shfl_xor_sync(0xffffffffu, sq, o);
    float rn = 1.f / fmaxf(sqrtf(sq), 1e-12f);
    for (int c = lane; c < EMB; c += 32)
        fout[(size_t)warp * EMB + c] = g_pool[(size_t)warp * EMB + c] * ic * rn;
}

// ------------------------- logits: out = (f0 @ f1^T) * 25 (exact fp32) ------
__global__ void k_logits(float* __restrict__ out) {
    __shared__ __align__(16) float As[16][64];
    __shared__ __align__(16) float Bs[16][64];
    int tx = threadIdx.x, ty = threadIdx.y;
    int tid = ty * 16 + tx;
    int rowBase = blockIdx.y * 64;
    int colBase = blockIdx.x * 64;
    float acc[4][4] = {};
    for (int kt = 0; kt < (EMB + 15) / 16; kt++) {
        int k0 = kt * 16;
        int c = tid & 15, r0 = tid >> 4;
#pragma unroll
        for (int p = 0; p < 4; p++) {
            int r = r0 + p * 16;
            int gc = k0 + c;
            As[c][r] = (gc < EMB) ? g_f0[(size_t)(rowBase + r) * EMB + gc] : 0.f;
            Bs[c][r] = (gc < EMB) ? g_f1[(size_t)(colBase + r) * EMB + gc] : 0.f;
        }
        __syncthreads();
#pragma unroll
        for (int kk = 0; kk < 16; kk++) {
            float4 a = *(const float4*)&As[kk][ty * 4];
            float4 b = *(const float4*)&Bs[kk][tx * 4];
            float ar[4] = {a.x, a.y, a.z, a.w};
            float br[4] = {b.x, b.y, b.z, b.w};
#pragma unroll
            for (int i = 0; i < 4; i++)
#pragma unroll
                for (int j = 0; j < 4; j++) acc[i][j] += ar[i] * br[j];
        }
        __syncthreads();
    }
#pragma unroll
    for (int i = 0; i < 4; i++)
#pragma unroll
        for (int j = 0; j < 4; j++)
            out[(size_t)(rowBase + ty * 4 + i) * NGRAPH + colBase + tx * 4 + j] =
                acc[i][j] * INV_TEMP;
}

// ------------------------- driver -------------------------------------------
extern "C" void kernel_launch(void* const* d_in, const int* in_sizes, int n_in,
                              void* d_out, int out_size) {
    (void)in_sizes; (void)n_in; (void)out_size;
    const int*   x[2]  = {(const int*)d_in[0], (const int*)d_in[4]};
    const int*   ei[2] = {(const int*)d_in[1], (const int*)d_in[5]};
    const int*   ea[2] = {(const int*)d_in[2], (const int*)d_in[6]};
    const int*   bt[2] = {(const int*)d_in[3], (const int*)d_in[7]};
    const float* ae1   = (const float*)d_in[8];
    const float* ae2   = (const float*)d_in[9];
    const float* ee1   = (const float*)d_in[10];
    const float* ee2   = (const float*)d_in[11];
    const float* w1    = (const float*)d_in[12];
    const float* b1    = (const float*)d_in[13];
    const float* w2    = (const float*)d_in[14];
    const float* b2    = (const float*)d_in[15];
    const float* gamma = (const float*)d_in[16];
    const float* beta  = (const float*)d_in[17];
    const float* pw    = (const float*)d_in[18];
    const float* pb    = (const float*)d_in[19];
    float* out = (float*)d_out;

    float *d_h, *d_agg, *d_hid;
    cudaGetSymbolAddress((void**)&d_h,   g_h);
    cudaGetSymbolAddress((void**)&d_agg, g_agg);
    cudaGetSymbolAddress((void**)&d_hid, g_hid);

    cudaFuncSetAttribute(k_gemm_tc, cudaFuncAttributeMaxDynamicSharedMemorySize,
                         SMEM_TC);

    const int NCH = NODES * CH4;
    dim3 grid1((HID + BN - 1) / BN, (NODES + BM - 1) / BM);
    dim3 grid2((EMB + BN - 1) / BN, (NODES + BM - 1) / BM);

    const float* selfs1[NLAYERS];
    const float* selfs2[NLAYERS];
    for (int l = 0; l < NLAYERS; l++) {
        selfs1[l] = ee1 + (size_t)(l * 6 + 4) * EMB;
        selfs2[l] = ee2 + (size_t)(l * 3 + 0) * EMB;
    }

    for (int br = 0; br < 2; br++) {
        k_init_h<<<(NCH + 255) / 256, 256>>>(x[br], ae1, ae2, selfs1[0], selfs2[0]);
        for (int l = 0; l < NLAYERS; l++) {
            k_edge_scatter<<<2048, 256>>>(ei[br], ea[br], ee1, ee2, l);
            k_gemm_tc<<<grid1, 256, SMEM_TC>>>(d_agg, w1 + (size_t)l * EMB * HID,
                                               b1 + (size_t)l * HID, d_hid,
                                               NODES, HID, EMB, 1);
            k_gemm_tc<<<grid2, 256, SMEM_TC>>>(d_hid, w2 + (size_t)l * HID * EMB,
                                               b2 + (size_t)l * EMB, d_h,
                                               NODES, EMB, HID, 0);
            k_zero600<<<1, 640>>>();
            k_bn_reduce<<<(NODES + 255) / 256, 320>>>();
            int last = (l == NLAYERS - 1);
            k_bn_norm<<<(NCH + 255) / 256, 256>>>(
                gamma + (size_t)l * EMB, beta + (size_t)l * EMB,
                last ? nullptr : selfs1[l + 1], last ? nullptr : selfs2[l + 1],
                !last);
        }
        k_gemm_tc<<<grid2, 256, SMEM_TC>>>(d_h, pw, pb, d_agg, NODES, EMB, EMB, 0);
        k_zero_pool<<<(NGRAPH * EMB + 255) / 256, 256>>>();
        k_pool_scatter<<<(NCH + 255) / 256, 256>>>(bt[br]);
        k_count<<<(NODES + 255) / 256, 256>>>(bt[br]);
        k_finalize<<<(NGRAPH * 32 + 255) / 256, 256>>>(br);
    }
    k_logits<<<dim3(NGRAPH / 64, NGRAPH / 64), dim3(16, 16)>>>(out);
}